// round 1
// baseline (speedup 1.0000x reference)
#include <cuda_runtime.h>
#include <cuda_bf16.h>
#include <cstdint>

#define LAMBDA_COORD 5.0f
#define LAMBDA_NOOBJ 0.5f
#define EPS 1e-9f
#define WARPS_PER_BLOCK 8

// scratch for per-block partial sums (max B=65536 -> 8192 blocks; pad)
__device__ double g_partial[16384];

__device__ __forceinline__ float bbox_iou(float px, float py, float pr,
                                          float gx, float gy, float gr) {
    float l1 = px - pr, r1 = px + pr, t1 = py - pr, b1 = py + pr;
    float l2 = gx - gr, r2 = gx + gr, t2 = gy - gr, b2 = gy + gr;
    float iw = fmaxf(fminf(r1, r2) - fmaxf(l1, l2), 0.0f);
    float ih = fmaxf(fminf(b1, b2) - fmaxf(t1, t2), 0.0f);
    float inter = iw * ih;
    float a1 = (r1 - l1) * (b1 - t1);
    float a2 = (r2 - l2) * (b2 - t2);
    return inter / (a1 + a2 - inter + EPS);
}

__global__ void __launch_bounds__(WARPS_PER_BLOCK * 32)
yolo_loss_kernel(const float* __restrict__ pred,
                 const int*   __restrict__ label_rc,
                 const float* __restrict__ label_box,
                 int B) {
    __shared__ float sh[WARPS_PER_BLOCK * 512];
    __shared__ double blocksum[WARPS_PER_BLOCK];

    const int warp = threadIdx.x >> 5;
    const int lane = threadIdx.x & 31;
    const int b = blockIdx.x * WARPS_PER_BLOCK + warp;

    float acc = 0.0f;

    if (b < B) {
        // ---- 1. stream this batch's 2KB pred slab into shared (coalesced f4) ----
        const float4* p4 = reinterpret_cast<const float4*>(pred + (size_t)b * 512);
        float4* s4 = reinterpret_cast<float4*>(sh + warp * 512);
#pragma unroll
        for (int i = 0; i < 4; i++) {
            s4[lane + 32 * i] = p4[lane + 32 * i];
        }
        __syncwarp();

        // ---- 2. labels: lanes 0..15, one label each; build occupancy bitmask ----
        unsigned mlo = 0, mhi = 0;
        int cell_idx = 0;
        float gx = 0.f, gy = 0.f, gr = 0.f;
        if (lane < 16) {
            int2 rcv = reinterpret_cast<const int2*>(label_rc)[(size_t)b * 16 + lane];
            const float* bx = label_box + ((size_t)b * 16 + lane) * 3;
            gx = bx[0]; gy = bx[1]; gr = bx[2];
            cell_idx = rcv.x * 8 + rcv.y;
            if (cell_idx < 32) mlo = 1u << cell_idx;
            else               mhi = 1u << (cell_idx - 32);
        }
        mlo = __reduce_or_sync(0xffffffffu, mlo);
        mhi = __reduce_or_sync(0xffffffffu, mhi);

        // ---- 3. per-label coord + conf losses ----
        if (lane < 16) {
            const float* pb = sh + warp * 512 + cell_idx * 8;
            float p0 = pb[0], p1 = pb[1], p2 = pb[2], p3 = pb[3];
            float q0 = pb[4], q1 = pb[5], q2 = pb[6], q3 = pb[7];

            float iou1 = bbox_iou(p0, p1, p2, gx, gy, gr);
            float iou2 = bbox_iou(q0, q1, q2, gx, gy, gr);
            bool swp = iou2 > iou1;

            float cx   = swp ? q0 : p0;
            float cy   = swp ? q1 : p1;
            float cr   = swp ? q2 : p2;
            float conf = swp ? q3 : p3;
            float ucnf = swp ? p3 : q3;
            float big  = swp ? iou2 : iou1;
            float sml  = swp ? iou1 : iou2;

            float dx = cx - gx, dy = cy - gy, dr = cr - gr;
            acc += LAMBDA_COORD * (dx * dx + dy * dy + dr * dr);
            float dc = big - conf;
            acc += dc * dc;
            float du = sml - ucnf;
            acc += LAMBDA_NOOBJ * du * du;
        }

        // ---- 4. noobj term: each lane handles cells 2*lane, 2*lane+1 ----
#pragma unroll
        for (int k = 0; k < 2; k++) {
            int cell = 2 * lane + k;
            bool obj = (cell < 32) ? ((mlo >> cell) & 1u)
                                   : ((mhi >> (cell - 32)) & 1u);
            if (!obj) {
                float c3 = sh[warp * 512 + cell * 8 + 3];
                float c7 = sh[warp * 512 + cell * 8 + 7];
                acc += LAMBDA_NOOBJ * (c3 * c3 + c7 * c7);
            }
        }
    }

    // ---- 5. warp reduce ----
#pragma unroll
    for (int o = 16; o > 0; o >>= 1)
        acc += __shfl_xor_sync(0xffffffffu, acc, o);
    if (lane == 0) blocksum[warp] = (double)acc;
    __syncthreads();
    if (threadIdx.x == 0) {
        double s = 0.0;
#pragma unroll
        for (int w = 0; w < WARPS_PER_BLOCK; w++) s += blocksum[w];
        g_partial[blockIdx.x] = s;
    }
}

__global__ void final_reduce_kernel(int nb, int B, float* out) {
    __shared__ double smem[256];
    double s = 0.0;
    for (int i = threadIdx.x; i < nb; i += 256) s += g_partial[i];
    smem[threadIdx.x] = s;
    __syncthreads();
#pragma unroll
    for (int o = 128; o > 0; o >>= 1) {
        if (threadIdx.x < o) smem[threadIdx.x] += smem[threadIdx.x + o];
        __syncthreads();
    }
    if (threadIdx.x == 0) out[0] = (float)(smem[0] / (double)B);
}

extern "C" void kernel_launch(void* const* d_in, const int* in_sizes, int n_in,
                              void* d_out, int out_size) {
    const float* pred      = (const float*)d_in[0];
    const int*   label_rc  = (const int*)d_in[1];
    const float* label_box = (const float*)d_in[2];
    float* out = (float*)d_out;

    int B = in_sizes[0] / 512;  // pred is [B, 8, 8, 8]
    int nb = (B + WARPS_PER_BLOCK - 1) / WARPS_PER_BLOCK;

    yolo_loss_kernel<<<nb, WARPS_PER_BLOCK * 32>>>(pred, label_rc, label_box, B);
    final_reduce_kernel<<<1, 256>>>(nb, B, out);
}

// round 2
// speedup vs baseline: 1.1902x; 1.1902x over previous
#include <cuda_runtime.h>
#include <cuda_bf16.h>
#include <cstdint>

#define LAMBDA_COORD 5.0f
#define LAMBDA_NOOBJ 0.5f
#define EPS 1e-9f
#define WARPS_PER_BLOCK 8
#define NBLK 1184  // 148 SMs x 8 blocks = one full wave

__device__ double g_partial[NBLK];
__device__ unsigned g_count = 0;

__device__ __forceinline__ float bbox_iou(float px, float py, float pr,
                                          float gx, float gy, float gr) {
    float l1 = px - pr, r1 = px + pr, t1 = py - pr, b1 = py + pr;
    float l2 = gx - gr, r2 = gx + gr, t2 = gy - gr, b2 = gy + gr;
    float iw = fmaxf(fminf(r1, r2) - fmaxf(l1, l2), 0.0f);
    float ih = fmaxf(fminf(b1, b2) - fmaxf(t1, t2), 0.0f);
    float inter = iw * ih;
    float a1 = (r1 - l1) * (b1 - t1);
    float a2 = (r2 - l2) * (b2 - t2);
    return inter / (a1 + a2 - inter + EPS);
}

__global__ void __launch_bounds__(WARPS_PER_BLOCK * 32)
yolo_loss_kernel(const float* __restrict__ pred,
                 const int*   __restrict__ label_rc,
                 const float* __restrict__ label_box,
                 int B, float* __restrict__ out) {
    __shared__ float sh[WARPS_PER_BLOCK * 512];
    __shared__ double blocksum[WARPS_PER_BLOCK];
    __shared__ int islast;

    const int warp = threadIdx.x >> 5;
    const int lane = threadIdx.x & 31;
    const int NW = NBLK * WARPS_PER_BLOCK;       // total warps in grid
    int b = blockIdx.x * WARPS_PER_BLOCK + warp; // this warp's first batch

    float* shw = sh + warp * 512;
    float4* s4 = reinterpret_cast<float4*>(shw);

    float acc = 0.0f;

    // ---- prefetch first batch's pred slab into registers ----
    float4 r0, r1, r2, r3;
    if (b < B) {
        const float4* p4 = reinterpret_cast<const float4*>(pred + (size_t)b * 512);
        r0 = p4[lane]; r1 = p4[lane + 32]; r2 = p4[lane + 64]; r3 = p4[lane + 96];
    }

    while (b < B) {
        const int bn = b + NW;

        // stage current batch into shared (conflict-free f4 stores)
        s4[lane] = r0; s4[lane + 32] = r1; s4[lane + 64] = r2; s4[lane + 96] = r3;

        // label loads for current batch (overlaps with prefetch below)
        unsigned mlo = 0, mhi = 0;
        int cell_idx = 0;
        float gx = 0.f, gy = 0.f, gr = 0.f;
        if (lane < 16) {
            int2 rcv = reinterpret_cast<const int2*>(label_rc)[(size_t)b * 16 + lane];
            const float* bx = label_box + ((size_t)b * 16 + lane) * 3;
            gx = bx[0]; gy = bx[1]; gr = bx[2];
            cell_idx = rcv.x * 8 + rcv.y;
            if (cell_idx < 32) mlo = 1u << cell_idx;
            else               mhi = 1u << (cell_idx - 32);
        }

        // issue NEXT batch's global loads now — keeps DRAM pipe full
        if (bn < B) {
            const float4* p4 = reinterpret_cast<const float4*>(pred + (size_t)bn * 512);
            r0 = p4[lane]; r1 = p4[lane + 32]; r2 = p4[lane + 64]; r3 = p4[lane + 96];
        }

        mlo = __reduce_or_sync(0xffffffffu, mlo);
        mhi = __reduce_or_sync(0xffffffffu, mhi);
        __syncwarp();

        // ---- per-label coord + conf losses (lanes 0..15) ----
        if (lane < 16) {
            const float4* pb4 = reinterpret_cast<const float4*>(shw + cell_idx * 8);
            float4 a = pb4[0];   // p0..p3
            float4 c = pb4[1];   // q0..q3

            float iou1 = bbox_iou(a.x, a.y, a.z, gx, gy, gr);
            float iou2 = bbox_iou(c.x, c.y, c.z, gx, gy, gr);
            bool swp = iou2 > iou1;

            float cx   = swp ? c.x : a.x;
            float cy   = swp ? c.y : a.y;
            float cr   = swp ? c.z : a.z;
            float conf = swp ? c.w : a.w;
            float ucnf = swp ? a.w : c.w;
            float big  = swp ? iou2 : iou1;
            float sml  = swp ? iou1 : iou2;

            float dx = cx - gx, dy = cy - gy, dr = cr - gr;
            acc += LAMBDA_COORD * (dx * dx + dy * dy + dr * dr);
            float dc = big - conf;
            acc += dc * dc;
            float du = sml - ucnf;
            acc += LAMBDA_NOOBJ * du * du;
        }

        // ---- noobj term: each lane handles 2 cells ----
#pragma unroll
        for (int k = 0; k < 2; k++) {
            int cell = 2 * lane + k;
            bool obj = (cell < 32) ? ((mlo >> cell) & 1u)
                                   : ((mhi >> (cell - 32)) & 1u);
            if (!obj) {
                float c3 = shw[cell * 8 + 3];
                float c7 = shw[cell * 8 + 7];
                acc += LAMBDA_NOOBJ * (c3 * c3 + c7 * c7);
            }
        }
        __syncwarp();  // protect shared before next overwrite
        b = bn;
    }

    // ---- warp reduce -> block reduce ----
#pragma unroll
    for (int o = 16; o > 0; o >>= 1)
        acc += __shfl_xor_sync(0xffffffffu, acc, o);
    if (lane == 0) blocksum[warp] = (double)acc;
    __syncthreads();

    if (threadIdx.x == 0) {
        double s = 0.0;
#pragma unroll
        for (int w = 0; w < WARPS_PER_BLOCK; w++) s += blocksum[w];
        g_partial[blockIdx.x] = s;
        __threadfence();
        unsigned ticket = atomicAdd(&g_count, 1u);
        islast = (ticket == (unsigned)(gridDim.x - 1)) ? 1 : 0;
    }
    __syncthreads();

    // ---- last block folds the 1184 partials (deterministic fixed tree) ----
    if (islast) {
        __shared__ double red[256];
        double s = 0.0;
        for (int i = threadIdx.x; i < NBLK; i += 256)
            s += *((volatile double*)&g_partial[i]);
        red[threadIdx.x] = s;
        __syncthreads();
#pragma unroll
        for (int o = 128; o > 0; o >>= 1) {
            if (threadIdx.x < o) red[threadIdx.x] += red[threadIdx.x + o];
            __syncthreads();
        }
        if (threadIdx.x == 0) {
            out[0] = (float)(red[0] / (double)B);
            g_count = 0;  // reset for next graph replay
        }
    }
}

extern "C" void kernel_launch(void* const* d_in, const int* in_sizes, int n_in,
                              void* d_out, int out_size) {
    const float* pred      = (const float*)d_in[0];
    const int*   label_rc  = (const int*)d_in[1];
    const float* label_box = (const float*)d_in[2];
    float* out = (float*)d_out;

    int B = in_sizes[0] / 512;  // pred is [B, 8, 8, 8]

    yolo_loss_kernel<<<NBLK, WARPS_PER_BLOCK * 32>>>(pred, label_rc, label_box, B, out);
}

// round 4
// speedup vs baseline: 1.3944x; 1.1716x over previous
#include <cuda_runtime.h>
#include <cuda_bf16.h>
#include <cstdint>

#define LAMBDA_COORD 5.0f
#define LAMBDA_NOOBJ 0.5f
#define EPS 1e-9f
#define WPB 8                 // warps per block
#define NSTAGE 3              // cp.async pipeline depth
#define NBLK 592              // 148 SMs * 4 blocks = one resident wave
#define SLAB_FLOATS 512       // 8*8*8 floats per batch
#define STAGE_BYTES 2048

__device__ double g_partial[NBLK];
__device__ unsigned g_count = 0;

__device__ __forceinline__ void cp_async16(uint32_t saddr, const void* g) {
    asm volatile("cp.async.cg.shared.global [%0], [%1], 16;" :: "r"(saddr), "l"(g));
}
__device__ __forceinline__ void cp_commit() {
    asm volatile("cp.async.commit_group;");
}
template <int N>
__device__ __forceinline__ void cp_wait() {
    asm volatile("cp.async.wait_group %0;" :: "n"(N));
}

__device__ __forceinline__ float bbox_iou(float px, float py, float pr,
                                          float gx, float gy, float gr) {
    float l1 = px - pr, r1 = px + pr, t1 = py - pr, b1 = py + pr;
    float l2 = gx - gr, r2 = gx + gr, t2 = gy - gr, b2 = gy + gr;
    float iw = fmaxf(fminf(r1, r2) - fmaxf(l1, l2), 0.0f);
    float ih = fmaxf(fminf(b1, b2) - fmaxf(t1, t2), 0.0f);
    float inter = iw * ih;
    float a1 = (r1 - l1) * (b1 - t1);
    float a2 = (r2 - l2) * (b2 - t2);
    return inter / (a1 + a2 - inter + EPS);
}

__global__ void __launch_bounds__(WPB * 32, 4)
yolo_loss_kernel(const float* __restrict__ pred,
                 const int*   __restrict__ label_rc,
                 const float* __restrict__ label_box,
                 int B, float* __restrict__ out) {
    // Dynamic smem only: WPB * NSTAGE * 512 floats = 48 KB exactly.
    // NO static __shared__ — the post-loop reduction reuses this buffer.
    extern __shared__ float dsh[];

    const int warp = threadIdx.x >> 5;
    const int lane = threadIdx.x & 31;
    const int NW = NBLK * WPB;
    const int b0 = blockIdx.x * WPB + warp;

    float* shw = dsh + warp * (NSTAGE * SLAB_FLOATS);
    uint32_t s_base = (uint32_t)__cvta_generic_to_shared(shw);

    float acc = 0.0f;

    auto issue = [&](int stage, int bb) {
        if (bb < B) {
            const char* g = (const char*)(pred + (size_t)bb * SLAB_FLOATS) + lane * 16;
            uint32_t sa = s_base + stage * STAGE_BYTES + lane * 16;
            cp_async16(sa,        g);
            cp_async16(sa + 512,  g + 512);
            cp_async16(sa + 1024, g + 1024);
            cp_async16(sa + 1536, g + 1536);
        }
        cp_commit();
    };

    // prologue: fill stages 0 and 1
    issue(0, b0);
    issue(1, b0 + NW);

    // label prefetch for first batch
    int2 nrc = make_int2(0, 0);
    float ngx = 0.f, ngy = 0.f, ngr = 0.f;
    if (lane < 16 && b0 < B) {
        nrc = reinterpret_cast<const int2*>(label_rc)[(size_t)b0 * 16 + lane];
        const float* bx = label_box + ((size_t)b0 * 16 + lane) * 3;
        ngx = bx[0]; ngy = bx[1]; ngr = bx[2];
    }

    int stage = 0;
    for (int b = b0; b < B; b += NW) {
        // keep pipeline full: stage (stage+2)%3 <- batch b+2*NW
        int is = stage + 2; if (is >= NSTAGE) is -= NSTAGE;
        issue(is, b + 2 * NW);

        int2 rc = nrc;
        float gx = ngx, gy = ngy, gr = ngr;

        // prefetch next batch's labels
        if (lane < 16 && b + NW < B) {
            nrc = reinterpret_cast<const int2*>(label_rc)[(size_t)(b + NW) * 16 + lane];
            const float* bx = label_box + ((size_t)(b + NW) * 16 + lane) * 3;
            ngx = bx[0]; ngy = bx[1]; ngr = bx[2];
        }

        // occupancy bitmask (duplicates collapse)
        unsigned mlo = 0, mhi = 0;
        int cell_idx = 0;
        if (lane < 16) {
            cell_idx = rc.x * 8 + rc.y;
            if (cell_idx < 32) mlo = 1u << cell_idx;
            else               mhi = 1u << (cell_idx - 32);
        }
        mlo = __reduce_or_sync(0xffffffffu, mlo);
        mhi = __reduce_or_sync(0xffffffffu, mhi);

        // wait for this stage's data, make visible warp-wide
        cp_wait<NSTAGE - 1>();
        __syncwarp();

        const float4* st4 = reinterpret_cast<const float4*>(shw + stage * SLAB_FLOATS);

        // ---- per-label coord + conf losses (lanes 0..15) ----
        if (lane < 16) {
            float4 a = st4[cell_idx * 2];       // p0..p3
            float4 c = st4[cell_idx * 2 + 1];   // q0..q3

            float iou1 = bbox_iou(a.x, a.y, a.z, gx, gy, gr);
            float iou2 = bbox_iou(c.x, c.y, c.z, gx, gy, gr);
            bool swp = iou2 > iou1;

            float cx   = swp ? c.x : a.x;
            float cy   = swp ? c.y : a.y;
            float cr   = swp ? c.z : a.z;
            float conf = swp ? c.w : a.w;
            float ucnf = swp ? a.w : c.w;
            float big  = swp ? iou2 : iou1;
            float sml  = swp ? iou1 : iou2;

            float dx = cx - gx, dy = cy - gy, dr = cr - gr;
            acc += LAMBDA_COORD * (dx * dx + dy * dy + dr * dr);
            float dc = big - conf;
            acc += dc * dc;
            float du = sml - ucnf;
            acc += LAMBDA_NOOBJ * du * du;
        }

        // ---- noobj: conflict-free float4 scan; ch3/ch7 are .w of f4 #2c/#2c+1 ----
#pragma unroll
        for (int k = 0; k < 4; k++) {
            int j = lane + 32 * k;
            float4 v = st4[j];
            int cell = j >> 1;
            bool obj = (cell < 32) ? ((mlo >> cell) & 1u)
                                   : ((mhi >> (cell - 32)) & 1u);
            if (!obj) acc += LAMBDA_NOOBJ * v.w * v.w;
        }

        stage = stage + 1; if (stage == NSTAGE) stage = 0;
    }

    // ---- drain all outstanding cp.asyncs, then reuse dsh for reductions ----
    cp_wait<0>();
    __syncthreads();   // orders every warp's async writes before scratch reuse

    double* blocksum = reinterpret_cast<double*>(dsh);        // 8 doubles
    int*    islast_p = reinterpret_cast<int*>(dsh + 16);      // 1 int
    double* red      = reinterpret_cast<double*>(dsh + 32);   // 256 doubles

    // warp reduce
#pragma unroll
    for (int o = 16; o > 0; o >>= 1)
        acc += __shfl_xor_sync(0xffffffffu, acc, o);
    if (lane == 0) blocksum[warp] = (double)acc;
    __syncthreads();

    if (threadIdx.x == 0) {
        double s = 0.0;
#pragma unroll
        for (int w = 0; w < WPB; w++) s += blocksum[w];
        g_partial[blockIdx.x] = s;
        __threadfence();
        unsigned ticket = atomicAdd(&g_count, 1u);
        *islast_p = (ticket == (unsigned)(gridDim.x - 1)) ? 1 : 0;
    }
    __syncthreads();

    // ---- last block folds partials (deterministic fixed tree) ----
    if (*islast_p) {
        double s = 0.0;
        for (int i = threadIdx.x; i < NBLK; i += 256)
            s += *((volatile double*)&g_partial[i]);
        red[threadIdx.x] = s;
        __syncthreads();
#pragma unroll
        for (int o = 128; o > 0; o >>= 1) {
            if (threadIdx.x < o) red[threadIdx.x] += red[threadIdx.x + o];
            __syncthreads();
        }
        if (threadIdx.x == 0) {
            out[0] = (float)(red[0] / (double)B);
            g_count = 0;  // reset for next graph replay
        }
    }
}

extern "C" void kernel_launch(void* const* d_in, const int* in_sizes, int n_in,
                              void* d_out, int out_size) {
    const float* pred      = (const float*)d_in[0];
    const int*   label_rc  = (const int*)d_in[1];
    const float* label_box = (const float*)d_in[2];
    float* out = (float*)d_out;

    int B = in_sizes[0] / SLAB_FLOATS;  // pred is [B, 8, 8, 8]
    size_t smem = (size_t)WPB * NSTAGE * SLAB_FLOATS * sizeof(float);  // 48 KB, no static

    yolo_loss_kernel<<<NBLK, WPB * 32, smem>>>(pred, label_rc, label_box, B, out);
}